// round 17
// baseline (speedup 1.0000x reference)
#include <cuda_runtime.h>
#include <cuda_fp16.h>
#include <cstdint>
#include <cstddef>

#define MDIM 16
#define KDIM 8192
#define NDIM 8192
#define KSPLIT 8
#define KPER 1024              // k per split
#define NGRP 8                 // 128-k groups per split
#define NT 32                  // n tiles (256 rows each)
#define THREADS 256
#define N8W 4                  // n8 blocks per warp (8 warps x 4 = 32 per tile)

// smem: frag [64 blocks][32 lanes] uint4 (32768B), then xraw scratch 16x516 floats
#define RAW_ROW 516
#define SM_XRAW_OFF 32768
#define SM_TOTAL (32768 + 16 * 516 * 4)   // 65792 B -> 3 CTAs/SM

__device__ __align__(16) float g_partial[KSPLIT][1024][128];   // 4 MB

__device__ __forceinline__ void mma16816(float4& c,
                                         uint32_t a0, uint32_t a1, uint32_t a2, uint32_t a3,
                                         uint32_t b0, uint32_t b1) {
    asm volatile(
        "mma.sync.aligned.m16n8k16.row.col.f32.f16.f16.f32 "
        "{%0,%1,%2,%3},{%4,%5,%6,%7},{%8,%9},{%0,%1,%2,%3};"
        : "+f"(c.x), "+f"(c.y), "+f"(c.z), "+f"(c.w)
        : "r"(a0), "r"(a1), "r"(a2), "r"(a3), "r"(b0), "r"(b1));
}

// one int32 (8 nibbles) -> half2 {q[c], q[c+4]} * s + z  (bias removed exactly)
__device__ __forceinline__ uint32_t dq2(uint32_t w, uint32_t c4, __half2 s2, __half2 z2) {
    uint32_t t = ((w >> c4) & 0x000F000Fu) | 0x64006400u;
    uint32_t bu = 0x64006400u;
    __half2 q = __hsub2(*reinterpret_cast<__half2*>(&t), *reinterpret_cast<__half2*>(&bu));
    __half2 r = __hfma2(q, s2, z2);
    return *reinterpret_cast<uint32_t*>(&r);
}

__global__ void __launch_bounds__(THREADS, 3) wq_gemm(
    const float* __restrict__ x, const int* __restrict__ qw,
    const float* __restrict__ scales, const float* __restrict__ zeros) {
    extern __shared__ char smem[];
    uint4* frag = reinterpret_cast<uint4*>(smem);
    float* xraw = reinterpret_cast<float*>(smem + SM_XRAW_OFF);
    const int tid = threadIdx.x;
    const int nt = blockIdx.x & (NT - 1);
    const int ks = blockIdx.x >> 5;

    // ---- prologue: pack x A-fragments in two 512-k sections ----
    // virtual-k permutation: 2c <-> c, 2c+1 <-> c+4
#pragma unroll 1
    for (int s = 0; s < 2; s++) {
        const float* xg = x + (size_t)ks * KPER + s * 512;
#pragma unroll
        for (int i = 0; i < 8; i++) {
            int e = tid + i * THREADS;      // 0..2047 float4 slots
            int r = e >> 7;                 // 128 float4 per row
            int kk = (e & 127) << 2;
            float4 v = *reinterpret_cast<const float4*>(xg + (size_t)r * KDIM + kk);
            *reinterpret_cast<float4*>(xraw + r * RAW_ROW + kk) = v;
        }
        __syncthreads();
#pragma unroll
        for (int j = 0; j < 4; j++) {
            int e = tid + j * THREADS;      // 0..1023 = (local block, lane)
            int bl = e >> 5, l = e & 31;
            int r = l >> 2, c = l & 3, kb = bl * 16;
            const float* r0 = xraw + r * RAW_ROW + kb;
            const float* r1 = xraw + (r + 8) * RAW_ROW + kb;
            __half2 a0 = __floats2half2_rn(r0[c], r0[c + 4]);
            __half2 a1 = __floats2half2_rn(r1[c], r1[c + 4]);
            __half2 a2 = __floats2half2_rn(r0[8 + c], r0[12 + c]);
            __half2 a3 = __floats2half2_rn(r1[8 + c], r1[12 + c]);
            uint4 f;
            f.x = *reinterpret_cast<uint32_t*>(&a0);
            f.y = *reinterpret_cast<uint32_t*>(&a1);
            f.z = *reinterpret_cast<uint32_t*>(&a2);
            f.w = *reinterpret_cast<uint32_t*>(&a3);
            frag[(s * 32 + bl) * 32 + l] = f;
        }
        __syncthreads();
    }

    // ---- main loop ----
    const int wid = tid >> 5, lane = tid & 31;
    const int nb0 = nt * 32 + wid * N8W;
    const int r_in8 = lane >> 2;
    const uint32_t c4 = (uint32_t)(lane & 3) * 4;
    const int row0 = nb0 * 8 + r_in8;

    // qweight as uint4: row stride 256; ksplit offset = 1024k = 32 uint4
    const uint4* qp = reinterpret_cast<const uint4*>(qw) + (size_t)row0 * 256 + ks * 32;

    float4 acc[N8W];
#pragma unroll
    for (int i = 0; i < N8W; i++) acc[i] = make_float4(0.f, 0.f, 0.f, 0.f);

#pragma unroll 1
    for (int g = 0; g < NGRP; g++) {
        __half2 s2[N8W], z2[N8W];
        const float* sp = scales + (size_t)(ks * NGRP + g) * NDIM + row0;
        const float* zp = zeros + (size_t)(ks * NGRP + g) * NDIM + row0;
#pragma unroll
        for (int i = 0; i < N8W; i++) {
            s2[i] = __half2half2(__float2half_rn(sp[i * 8]));
            z2[i] = __half2half2(__float2half_rn(zp[i * 8]));
        }
#pragma unroll
        for (int p = 0; p < 4; p++) {       // 4 uint4 = 8 k16-blocks per group-row
            uint4 wq[N8W];
#pragma unroll
            for (int i = 0; i < N8W; i++)
                wq[i] = qp[(size_t)i * 2048 + g * 4 + p];
#pragma unroll
            for (int sub = 0; sub < 2; sub++) {
                uint4 ah = frag[((g * 8 + p * 2 + sub) << 5) + lane];
#pragma unroll
                for (int i = 0; i < N8W; i++) {
                    uint32_t w0 = sub ? wq[i].z : wq[i].x;
                    uint32_t w1 = sub ? wq[i].w : wq[i].y;
                    uint32_t b0 = dq2(w0, c4, s2[i], z2[i]);
                    uint32_t b1 = dq2(w1, c4, s2[i], z2[i]);
                    mma16816(acc[i], ah.x, ah.y, ah.z, ah.w, b0, b1);
                }
            }
        }
    }

    // ---- store partials ----
    const int off = r_in8 * 8 + (lane & 3) * 2;
#pragma unroll
    for (int i = 0; i < N8W; i++) {
        float* pb = &g_partial[ks][nb0 + i][0];
        *reinterpret_cast<float2*>(pb + off) = make_float2(acc[i].x, acc[i].y);
        *reinterpret_cast<float2*>(pb + 64 + off) = make_float2(acc[i].z, acc[i].w);
    }

    asm volatile("griddepcontrol.launch_dependents;");
}

// combine (PDL): preamble overlaps gemm; wait guarantees partial visibility
__global__ void __launch_bounds__(256) wq_combine(const float* __restrict__ bias,
                                                  float* __restrict__ out) {
    int t = blockIdx.x * 256 + threadIdx.x;     // 0..32767 float4 slots
    int nb = t >> 5;                            // n8 block (1024)
    int q = t & 31;                             // float4 index within 128
    int o = q * 4;
    int m = o >> 3;                             // 4-element span stays in one m
    int n = nb * 8 + (o & 7);                   // 4-aligned
    float4 b = *reinterpret_cast<const float4*>(bias + n);   // input, pre-wait OK

    asm volatile("griddepcontrol.wait;" ::: "memory");

    float4 s = b;
#pragma unroll
    for (int ks = 0; ks < KSPLIT; ks++) {
        float4 p = *reinterpret_cast<const float4*>(&g_partial[ks][nb][q * 4]);
        s.x += p.x; s.y += p.y; s.z += p.z; s.w += p.w;
    }
    *reinterpret_cast<float4*>(out + (size_t)m * NDIM + n) = s;
}

extern "C" void kernel_launch(void* const* d_in, const int* in_sizes, int n_in,
                              void* d_out, int out_size) {
    const float* x = (const float*)d_in[0];
    const int* qw = (const int*)d_in[1];
    const float* sc = (const float*)d_in[2];
    const float* zz = (const float*)d_in[3];
    const float* bias = (const float*)d_in[4];
    (void)in_sizes; (void)n_in; (void)out_size;

    cudaFuncSetAttribute(wq_gemm, cudaFuncAttributeMaxDynamicSharedMemorySize, SM_TOTAL);
    wq_gemm<<<NT * KSPLIT, THREADS, SM_TOTAL>>>(x, qw, sc, zz);

    cudaLaunchConfig_t cfg = {};
    cfg.gridDim = dim3(128, 1, 1);
    cfg.blockDim = dim3(256, 1, 1);
    cfg.dynamicSmemBytes = 0;
    cudaLaunchAttribute attrs[1];
    attrs[0].id = cudaLaunchAttributeProgrammaticStreamSerialization;
    attrs[0].val.programmaticStreamSerializationAllowed = 1;
    cfg.attrs = attrs;
    cfg.numAttrs = 1;
    cudaLaunchKernelEx(&cfg, wq_combine, bias, (float*)d_out);
}